// round 10
// baseline (speedup 1.0000x reference)
#include <cuda_runtime.h>
#include <cstdint>

// RandomStretchSqueeze: batched bilinear resample (half-pixel centers) to
// length L=floor(T*f), then center crop-or-pad back to T. B=512, T=65536.
//
// R10: CHUNK=2048 (R8's per-output amortization: fixed per-chunk cost /
// 8 outputs/thread) x CHUNKS=2 (R9's 18.4KB smem -> 8 blocks/SM). All
// prefetch groups issued in prologue; no buffer reuse; wait_group countdown.
// R9 showed CHUNK=1024 doubles fixed-cost/output (issue 81.9%, ALU 49.8%);
// R8 showed 36.9KB kills occupancy (66%). This is the corner of the plane
// with both properties.

#define RS_B 512
#define RS_T 65536
#define CHUNK 2048
#define CHUNKS 2
#define OUT_PER_BLOCK (CHUNK * CHUNKS)      // 4096
#define BLOCKS_PER_ROW 16                   // 65536 / 4096
#define WIN_FLOATS 2304                     // >= worst span (2281), 16B mult

// Per-chunk source window [s0, s0+4*nv4). nv4=0 for pure-pad chunks.
__device__ __forceinline__ void rs_window(int j_start, int L, int off, float scale,
                                          int& s0, int& nv4) {
    const int r_lo = j_start + off;
    const int r_hi = r_lo + CHUNK - 1;
    if (r_hi < 0 || r_lo >= L) { s0 = 0; nv4 = 0; return; }
    const int rc_lo = max(0, min(r_lo, L - 1));
    const int rc_hi = max(0, min(r_hi, L - 1));
    float x_lo = ((float)rc_lo + 0.5f) * scale - 0.5f;
    x_lo = fminf(fmaxf(x_lo, 0.0f), (float)(RS_T - 1));
    float x_hi = ((float)rc_hi + 0.5f) * scale - 0.5f;
    x_hi = fminf(fmaxf(x_hi, 0.0f), (float)(RS_T - 1));
    s0 = ((int)x_lo) & ~3;                  // 16B-aligned start
    int s1 = (int)x_hi + 2;                 // include x1 = floor+1
    if (s1 > RS_T) s1 = RS_T;
    nv4 = (s1 - s0 + 3) >> 2;               // <= 571 float4s
}

__device__ __forceinline__ void rs_prefetch(const float* __restrict__ row,
                                            float* __restrict__ buf,
                                            int s0, int nv4, int tid) {
    const char* g = (const char*)(row + s0);
    unsigned sa = (unsigned)__cvta_generic_to_shared(buf);
#pragma unroll
    for (int i = 0; i < 3; i++) {           // covers nv4 <= 768
        const int idx = tid + (i << 8);
        if (idx < nv4) {
            asm volatile("cp.async.cg.shared.global [%0], [%1], 16;\n"
                         :: "r"(sa + idx * 16), "l"(g + (size_t)idx * 16)
                         : "memory");
        }
    }
    asm volatile("cp.async.commit_group;\n" ::: "memory");  // always (count!)
}

template <int N>
__device__ __forceinline__ void rs_wait() {
    asm volatile("cp.async.wait_group %0;\n" :: "n"(N) : "memory");
}

__global__ void __launch_bounds__(256, 8)
rs_kernel(const float* __restrict__ in,
          const float* __restrict__ factors,
          float* __restrict__ out) {
    __shared__ float s_win[CHUNKS][WIN_FLOATS];   // 18.4 KB

    const int b    = blockIdx.x >> 4;               // row
    const int part = blockIdx.x & (BLOCKS_PER_ROW - 1);
    const int tid  = threadIdx.x;

    // ---- per-row constants (uniform) ----
    const float fv = __ldg(factors + b);
    // 65536.0f * fv is EXACT (pow-2 multiply); trunc matches astype(int32).
    int L = (int)(fv * (float)RS_T);
    if (L < 1) L = 1;
    const int off = (L >= RS_T) ? ((L - RS_T) >> 1) : (-((RS_T - L) >> 1));
    const float scale = __fdiv_rn((float)RS_T, (float)L);   // correctly rounded

    const float* __restrict__ row = in + ((size_t)b << 16);
    const int j_block = part * OUT_PER_BLOCK;
    float* __restrict__ oblk = out + ((size_t)b << 16) + j_block;

    // ---- prologue: compute all windows, issue ALL prefetch groups ----
    int s0a[CHUNKS];
#pragma unroll
    for (int c = 0; c < CHUNKS; c++) {
        int nv4;
        rs_window(j_block + c * CHUNK, L, off, scale, s0a[c], nv4);
        rs_prefetch(row, s_win[c], s0a[c], nv4, tid);    // group c
    }

    // ---- per-chunk: wait + gather (no buffer reuse, single sync) ----
#pragma unroll
    for (int c = 0; c < CHUNKS; c++) {
        if (c == 0) rs_wait<1>();
        else        rs_wait<0>();
        __syncthreads();                  // make staged data CTA-visible

        const int   r_lo = j_block + c * CHUNK + off;
        const int   r_hi = r_lo + CHUNK - 1;
        float* __restrict__ obase = oblk + c * CHUNK + tid;

        if (r_hi < 0 || r_lo >= L) {                // pure pad chunk
#pragma unroll
            for (int k = 0; k < 8; k++) obase[k << 8] = 0.0f;
        } else {
            const float* __restrict__ wbase = s_win[c] - s0a[c];
            const int rc_hi = max(0, min(r_hi, L - 1));
            float x_hi = ((float)rc_hi + 0.5f) * scale - 0.5f;
            x_hi = fminf(fmaxf(x_hi, 0.0f), (float)(RS_T - 1));
            // fast iff: all r valid, clamps provably no-ops, x0+1 staged
            const bool fast = (r_lo >= 1) && (r_hi < L) &&
                              (x_hi < (float)(RS_T - 1));
            if (fast) {
                // rf == (float)r exactly (r < 2^24; +256.0f adds exact), so
                // x is bit-identical to the validated arithmetic.
                float rf = (float)(r_lo + tid);
#pragma unroll
                for (int k = 0; k < 8; k++) {
                    const float x  = (rf + 0.5f) * scale - 0.5f;
                    const int   x0 = (int)x;        // x > 0 -> trunc == floor
                    const float w  = x - (float)x0;
                    const float a0 = wbase[x0];
                    const float a1 = wbase[x0 + 1];
                    obase[k << 8] = fmaf(w, a1 - a0, a0);
                    rf += 256.0f;
                }
            } else {
#pragma unroll
                for (int k = 0; k < 8; k++) {
                    const int r = r_lo + tid + (k << 8);
                    float v = 0.0f;
                    if ((unsigned)r < (unsigned)L) {
                        float x = ((float)r + 0.5f) * scale - 0.5f;
                        x = fminf(fmaxf(x, 0.0f), (float)(RS_T - 1));
                        const int   x0 = (int)x;
                        const float w  = x - (float)x0;
                        const int   x1 = min(x0 + 1, RS_T - 1); // staged
                        v = fmaf(w, wbase[x1] - wbase[x0], wbase[x0]);
                    }
                    obase[k << 8] = v;
                }
            }
        }
        // no trailing sync: buffers are never reused
    }
}

extern "C" void kernel_launch(void* const* d_in, const int* in_sizes, int n_in,
                              void* d_out, int out_size) {
    const float* inputs  = (const float*)d_in[0];   // [B, T] fp32
    const float* factors = (const float*)d_in[1];   // [B]    fp32
    float*       out     = (float*)d_out;           // [B, T] fp32

    const int grid = RS_B * BLOCKS_PER_ROW;         // 8192 blocks
    rs_kernel<<<grid, 256>>>(inputs, factors, out);
}

// round 12
// speedup vs baseline: 1.0014x; 1.0014x over previous
#include <cuda_runtime.h>
#include <cstdint>

// RandomStretchSqueeze: batched bilinear resample (half-pixel centers) to
// length L=floor(T*f), then center crop-or-pad back to T. B=512, T=65536.
//
// R11 (resubmit; prior run died to infra) = R10 (CHUNK=2048 x CHUNKS=2,
// full-prologue cp.async prefetch, no buffer reuse, 18.4KB smem -> 8
// blocks/SM) + STREAMING STORES (__stcs). Bench is pinned ~45us while
// kernel time is ~39us across shapes; the residual tracks L2 dirty-line
// writeback of the 128MB output between graph replays. evict-first stores
// drain output lines eagerly (overlapping writeback with execution) and
// stop 128MB of never-re-read dirty data from competing with the read
// stream for L2.

#define RS_B 512
#define RS_T 65536
#define CHUNK 2048
#define CHUNKS 2
#define OUT_PER_BLOCK (CHUNK * CHUNKS)      // 4096
#define BLOCKS_PER_ROW 16                   // 65536 / 4096
#define WIN_FLOATS 2304                     // >= worst span (2281), 16B mult

// Per-chunk source window [s0, s0+4*nv4). nv4=0 for pure-pad chunks.
__device__ __forceinline__ void rs_window(int j_start, int L, int off, float scale,
                                          int& s0, int& nv4) {
    const int r_lo = j_start + off;
    const int r_hi = r_lo + CHUNK - 1;
    if (r_hi < 0 || r_lo >= L) { s0 = 0; nv4 = 0; return; }
    const int rc_lo = max(0, min(r_lo, L - 1));
    const int rc_hi = max(0, min(r_hi, L - 1));
    float x_lo = ((float)rc_lo + 0.5f) * scale - 0.5f;
    x_lo = fminf(fmaxf(x_lo, 0.0f), (float)(RS_T - 1));
    float x_hi = ((float)rc_hi + 0.5f) * scale - 0.5f;
    x_hi = fminf(fmaxf(x_hi, 0.0f), (float)(RS_T - 1));
    s0 = ((int)x_lo) & ~3;                  // 16B-aligned start
    int s1 = (int)x_hi + 2;                 // include x1 = floor+1
    if (s1 > RS_T) s1 = RS_T;
    nv4 = (s1 - s0 + 3) >> 2;               // <= 571 float4s
}

__device__ __forceinline__ void rs_prefetch(const float* __restrict__ row,
                                            float* __restrict__ buf,
                                            int s0, int nv4, int tid) {
    const char* g = (const char*)(row + s0);
    unsigned sa = (unsigned)__cvta_generic_to_shared(buf);
#pragma unroll
    for (int i = 0; i < 3; i++) {           // covers nv4 <= 768
        const int idx = tid + (i << 8);
        if (idx < nv4) {
            asm volatile("cp.async.cg.shared.global [%0], [%1], 16;\n"
                         :: "r"(sa + idx * 16), "l"(g + (size_t)idx * 16)
                         : "memory");
        }
    }
    asm volatile("cp.async.commit_group;\n" ::: "memory");  // always (count!)
}

template <int N>
__device__ __forceinline__ void rs_wait() {
    asm volatile("cp.async.wait_group %0;\n" :: "n"(N) : "memory");
}

__global__ void __launch_bounds__(256, 8)
rs_kernel(const float* __restrict__ in,
          const float* __restrict__ factors,
          float* __restrict__ out) {
    __shared__ float s_win[CHUNKS][WIN_FLOATS];   // 18.4 KB

    const int b    = blockIdx.x >> 4;               // row
    const int part = blockIdx.x & (BLOCKS_PER_ROW - 1);
    const int tid  = threadIdx.x;

    // ---- per-row constants (uniform) ----
    const float fv = __ldg(factors + b);
    // 65536.0f * fv is EXACT (pow-2 multiply); trunc matches astype(int32).
    int L = (int)(fv * (float)RS_T);
    if (L < 1) L = 1;
    const int off = (L >= RS_T) ? ((L - RS_T) >> 1) : (-((RS_T - L) >> 1));
    const float scale = __fdiv_rn((float)RS_T, (float)L);   // correctly rounded

    const float* __restrict__ row = in + ((size_t)b << 16);
    const int j_block = part * OUT_PER_BLOCK;
    float* __restrict__ oblk = out + ((size_t)b << 16) + j_block;

    // ---- prologue: compute all windows, issue ALL prefetch groups ----
    int s0a[CHUNKS];
#pragma unroll
    for (int c = 0; c < CHUNKS; c++) {
        int nv4;
        rs_window(j_block + c * CHUNK, L, off, scale, s0a[c], nv4);
        rs_prefetch(row, s_win[c], s0a[c], nv4, tid);    // group c
    }

    // ---- per-chunk: wait + gather (no buffer reuse, single sync) ----
#pragma unroll
    for (int c = 0; c < CHUNKS; c++) {
        if (c == 0) rs_wait<1>();
        else        rs_wait<0>();
        __syncthreads();                  // make staged data CTA-visible

        const int   r_lo = j_block + c * CHUNK + off;
        const int   r_hi = r_lo + CHUNK - 1;
        float* __restrict__ obase = oblk + c * CHUNK + tid;

        if (r_hi < 0 || r_lo >= L) {                // pure pad chunk
#pragma unroll
            for (int k = 0; k < 8; k++) __stcs(obase + (k << 8), 0.0f);
        } else {
            const float* __restrict__ wbase = s_win[c] - s0a[c];
            const int rc_hi = max(0, min(r_hi, L - 1));
            float x_hi = ((float)rc_hi + 0.5f) * scale - 0.5f;
            x_hi = fminf(fmaxf(x_hi, 0.0f), (float)(RS_T - 1));
            // fast iff: all r valid, clamps provably no-ops, x0+1 staged
            const bool fast = (r_lo >= 1) && (r_hi < L) &&
                              (x_hi < (float)(RS_T - 1));
            if (fast) {
                // rf == (float)r exactly (r < 2^24; +256.0f adds exact), so
                // x is bit-identical to the validated arithmetic.
                float rf = (float)(r_lo + tid);
#pragma unroll
                for (int k = 0; k < 8; k++) {
                    const float x  = (rf + 0.5f) * scale - 0.5f;
                    const int   x0 = (int)x;        // x > 0 -> trunc == floor
                    const float w  = x - (float)x0;
                    const float a0 = wbase[x0];
                    const float a1 = wbase[x0 + 1];
                    __stcs(obase + (k << 8), fmaf(w, a1 - a0, a0));
                    rf += 256.0f;
                }
            } else {
#pragma unroll
                for (int k = 0; k < 8; k++) {
                    const int r = r_lo + tid + (k << 8);
                    float v = 0.0f;
                    if ((unsigned)r < (unsigned)L) {
                        float x = ((float)r + 0.5f) * scale - 0.5f;
                        x = fminf(fmaxf(x, 0.0f), (float)(RS_T - 1));
                        const int   x0 = (int)x;
                        const float w  = x - (float)x0;
                        const int   x1 = min(x0 + 1, RS_T - 1); // staged
                        v = fmaf(w, wbase[x1] - wbase[x0], wbase[x0]);
                    }
                    __stcs(obase + (k << 8), v);
                }
            }
        }
        // no trailing sync: buffers are never reused
    }
}

extern "C" void kernel_launch(void* const* d_in, const int* in_sizes, int n_in,
                              void* d_out, int out_size) {
    const float* inputs  = (const float*)d_in[0];   // [B, T] fp32
    const float* factors = (const float*)d_in[1];   // [B]    fp32
    float*       out     = (float*)d_out;           // [B, T] fp32

    const int grid = RS_B * BLOCKS_PER_ROW;         // 8192 blocks
    rs_kernel<<<grid, 256>>>(inputs, factors, out);
}